// round 3
// baseline (speedup 1.0000x reference)
#include <cuda_runtime.h>
#include <math.h>

// Problem constants
#define TT 8192      // tokens = B*S
#define HH 1024      // hidden
#define FF 2048      // intermediate
#define EE 8         // experts

#define BM 128
#define BN 64
#define BK 16
#define MTILES (TT / BM)   // 64

// Scratch (device globals — no allocation allowed)
__device__ int   g_counts[EE];
__device__ int   g_rows[EE * TT];          // pair_row (=2*token+k) list per expert
__device__ float g_wpair[2 * TT];          // combine weight per pair
__device__ float g_G[(size_t)2 * TT * FF]; // 134 MB intermediate: silu(xWg)*(xWu)

// ---------------------------------------------------------------------------
__device__ __forceinline__ void cp16(void* smem, const void* gmem) {
    unsigned s = (unsigned)__cvta_generic_to_shared(smem);
    asm volatile("cp.async.ca.shared.global [%0], [%1], 16;\n" :: "r"(s), "l"(gmem));
}
#define CP_COMMIT() asm volatile("cp.async.commit_group;\n")
#define CP_WAIT0()  asm volatile("cp.async.wait_group 0;\n")

// ---------------------------------------------------------------------------
// Zero out-accumulator and per-expert counters
// ---------------------------------------------------------------------------
__global__ void zero_kernel(float* __restrict__ out) {
    int i = blockIdx.x * blockDim.x + threadIdx.x;
    if (i < TT * HH) out[i] = 0.0f;
    if (i < EE) g_counts[i] = 0;
}

// ---------------------------------------------------------------------------
// Router: one warp per token. logits = x @ gate_w^T, softmax, top-2,
// normalized weights; builds per-expert gathered pair lists.
// ---------------------------------------------------------------------------
__global__ void router_kernel(const float* __restrict__ x,
                              const float* __restrict__ gw,
                              float* __restrict__ logits_out) {
    int warp = (blockIdx.x * blockDim.x + threadIdx.x) >> 5;
    int lane = threadIdx.x & 31;
    if (warp >= TT) return;
    const float* xr = x + (size_t)warp * HH;

    float acc[EE];
#pragma unroll
    for (int e = 0; e < EE; e++) acc[e] = 0.0f;

    for (int i = lane; i < HH; i += 32) {
        float xv = xr[i];
#pragma unroll
        for (int e = 0; e < EE; e++) acc[e] += xv * gw[e * HH + i];
    }
#pragma unroll
    for (int e = 0; e < EE; e++) {
#pragma unroll
        for (int off = 16; off; off >>= 1)
            acc[e] += __shfl_xor_sync(0xffffffffu, acc[e], off);
    }

    if (lane == 0) {
#pragma unroll
        for (int e = 0; e < EE; e++) logits_out[(size_t)warp * EE + e] = acc[e];

        float m = acc[0];
#pragma unroll
        for (int e = 1; e < EE; e++) m = fmaxf(m, acc[e]);
        float p[EE];
#pragma unroll
        for (int e = 0; e < EE; e++) p[e] = __expf(acc[e] - m);

        // top-2, lowest-index-first on ties (matches lax.top_k)
        int i1 = 0;
#pragma unroll
        for (int e = 1; e < EE; e++) if (p[e] > p[i1]) i1 = e;
        int i2 = (i1 == 0) ? 1 : 0;
#pragma unroll
        for (int e = 0; e < EE; e++) if (e != i1 && p[e] > p[i2]) i2 = e;

        float ws = p[i1] + p[i2];
        float w1 = p[i1] / ws;
        float w2 = p[i2] / ws;

        int r1 = atomicAdd(&g_counts[i1], 1);
        g_rows[i1 * TT + r1] = 2 * warp + 0;
        g_wpair[2 * warp + 0] = w1;
        int r2 = atomicAdd(&g_counts[i2], 1);
        g_rows[i2 * TT + r2] = 2 * warp + 1;
        g_wpair[2 * warp + 1] = w2;
    }
}

// ---------------------------------------------------------------------------
// GEMM1: per expert, gathered X rows [cnt,H] x Wg/Wu [H,F] -> G = silu(g)*u
// grid.x = EE*MTILES, grid.y = FF/BN. 256 thr, 8x4 microtile, dual-B,
// 2-stage cp.async pipeline.
// ---------------------------------------------------------------------------
__global__ __launch_bounds__(256)
void gemm1_kernel(const float* __restrict__ x,
                  const float* __restrict__ Wg,
                  const float* __restrict__ Wu) {
    int e  = blockIdx.x >> 6;      // / MTILES(64)
    int mt = blockIdx.x & 63;
    int cnt = g_counts[e];
    int m0 = mt * BM;
    if (m0 >= cnt) return;
    int n0 = blockIdx.y * BN;

    __shared__ float As[2][BM][BK];   // 8 KB x2
    __shared__ float Bg[2][BK][BN];   // 4 KB x2
    __shared__ float Bu[2][BK][BN];   // 4 KB x2

    int tid = threadIdx.x;
    // A-load: row-major [BM][BK]; per thread 2 float4 along k of one row.
    int arow = tid & 127;
    int akq  = tid >> 7;                 // 0..1 -> k quads {akq*2, akq*2+1}
    int r = m0 + arow;
    int rc = r < cnt ? r : (cnt - 1);
    int pr = g_rows[e * TT + rc];
    const float* xrow = x + (size_t)(pr >> 1) * HH;

    // B-load: 16 k-rows x (16 threads x float4) covers 16x64
    int bk  = tid >> 4;
    int bng = (tid & 15) * 4;
    const float* WgE = Wg + (size_t)e * HH * FF;
    const float* WuE = Wu + (size_t)e * HH * FF;

    int ty = tid >> 4, tx = tid & 15;    // 16 x 16 thread grid
    float accg[8][4], accu[8][4];
#pragma unroll
    for (int i = 0; i < 8; i++)
#pragma unroll
        for (int j = 0; j < 4; j++) { accg[i][j] = 0.f; accu[i][j] = 0.f; }

    // prologue: stage 0
    {
        cp16(&As[0][arow][(akq * 2 + 0) * 4], xrow + (akq * 2 + 0) * 4);
        cp16(&As[0][arow][(akq * 2 + 1) * 4], xrow + (akq * 2 + 1) * 4);
        cp16(&Bg[0][bk][bng], WgE + (size_t)bk * FF + n0 + bng);
        cp16(&Bu[0][bk][bng], WuE + (size_t)bk * FF + n0 + bng);
        CP_COMMIT();
    }

    const int NK = HH / BK;
    for (int ks = 0; ks < NK; ks++) {
        int buf = ks & 1;
        CP_WAIT0();
        __syncthreads();
        if (ks + 1 < NK) {
            int nb = buf ^ 1;
            int k1 = (ks + 1) * BK;
            cp16(&As[nb][arow][(akq * 2 + 0) * 4], xrow + k1 + (akq * 2 + 0) * 4);
            cp16(&As[nb][arow][(akq * 2 + 1) * 4], xrow + k1 + (akq * 2 + 1) * 4);
            cp16(&Bg[nb][bk][bng], WgE + (size_t)(k1 + bk) * FF + n0 + bng);
            cp16(&Bu[nb][bk][bng], WuE + (size_t)(k1 + bk) * FF + n0 + bng);
            CP_COMMIT();
        }
#pragma unroll
        for (int kk4 = 0; kk4 < 4; kk4++) {
            float4 a[8];
#pragma unroll
            for (int i = 0; i < 8; i++)
                a[i] = *(const float4*)&As[buf][ty * 8 + i][kk4 * 4];
#pragma unroll
            for (int kq = 0; kq < 4; kq++) {
                float4 bg4 = *(const float4*)&Bg[buf][kk4 * 4 + kq][tx * 4];
                float4 bu4 = *(const float4*)&Bu[buf][kk4 * 4 + kq][tx * 4];
#pragma unroll
                for (int i = 0; i < 8; i++) {
                    float av = (&a[i].x)[kq];
                    accg[i][0] += av * bg4.x;  accg[i][1] += av * bg4.y;
                    accg[i][2] += av * bg4.z;  accg[i][3] += av * bg4.w;
                    accu[i][0] += av * bu4.x;  accu[i][1] += av * bu4.y;
                    accu[i][2] += av * bu4.z;  accu[i][3] += av * bu4.w;
                }
            }
        }
        __syncthreads();
    }

#pragma unroll
    for (int i = 0; i < 8; i++) {
        int rr = m0 + ty * 8 + i;
        if (rr >= cnt) continue;
        int prr = g_rows[e * TT + rr];
        float4 o;
        float g0 = accg[i][0], g1 = accg[i][1], g2 = accg[i][2], g3 = accg[i][3];
        o.x = g0 / (1.0f + __expf(-g0)) * accu[i][0];
        o.y = g1 / (1.0f + __expf(-g1)) * accu[i][1];
        o.z = g2 / (1.0f + __expf(-g2)) * accu[i][2];
        o.w = g3 / (1.0f + __expf(-g3)) * accu[i][3];
        *(float4*)&g_G[(size_t)prr * FF + n0 + tx * 4] = o;
    }
}

// ---------------------------------------------------------------------------
// GEMM2: G rows [cnt,F] x Wd [F,H], scale by combine weight, atomicAdd -> out
// grid.x = EE*MTILES, grid.y = HH/BN. 2-stage cp.async pipeline.
// ---------------------------------------------------------------------------
__global__ __launch_bounds__(256)
void gemm2_kernel(const float* __restrict__ Wd,
                  float* __restrict__ out) {
    int e  = blockIdx.x >> 6;
    int mt = blockIdx.x & 63;
    int cnt = g_counts[e];
    int m0 = mt * BM;
    if (m0 >= cnt) return;
    int n0 = blockIdx.y * BN;

    __shared__ float As[2][BM][BK];
    __shared__ float Bs[2][BK][BN];

    int tid = threadIdx.x;
    int arow = tid & 127;
    int akq  = tid >> 7;
    int r = m0 + arow;
    int rc = r < cnt ? r : (cnt - 1);
    int pr = g_rows[e * TT + rc];
    const float* grow = g_G + (size_t)pr * FF;

    int bk  = tid >> 4;
    int bng = (tid & 15) * 4;
    const float* WdE = Wd + (size_t)e * FF * HH;

    int ty = tid >> 4, tx = tid & 15;
    float acc[8][4];
#pragma unroll
    for (int i = 0; i < 8; i++)
#pragma unroll
        for (int j = 0; j < 4; j++) acc[i][j] = 0.f;

    {
        cp16(&As[0][arow][(akq * 2 + 0) * 4], grow + (akq * 2 + 0) * 4);
        cp16(&As[0][arow][(akq * 2 + 1) * 4], grow + (akq * 2 + 1) * 4);
        cp16(&Bs[0][bk][bng], WdE + (size_t)bk * HH + n0 + bng);
        CP_COMMIT();
    }

    const int NK = FF / BK;
    for (int ks = 0; ks < NK; ks++) {
        int buf = ks & 1;
        CP_WAIT0();
        __syncthreads();
        if (ks + 1 < NK) {
            int nb = buf ^ 1;
            int k1 = (ks + 1) * BK;
            cp16(&As[nb][arow][(akq * 2 + 0) * 4], grow + k1 + (akq * 2 + 0) * 4);
            cp16(&As[nb][arow][(akq * 2 + 1) * 4], grow + k1 + (akq * 2 + 1) * 4);
            cp16(&Bs[nb][bk][bng], WdE + (size_t)(k1 + bk) * HH + n0 + bng);
            CP_COMMIT();
        }
#pragma unroll
        for (int kk4 = 0; kk4 < 4; kk4++) {
            float4 a[8];
#pragma unroll
            for (int i = 0; i < 8; i++)
                a[i] = *(const float4*)&As[buf][ty * 8 + i][kk4 * 4];
#pragma unroll
            for (int kq = 0; kq < 4; kq++) {
                float4 b4 = *(const float4*)&Bs[buf][kk4 * 4 + kq][tx * 4];
#pragma unroll
                for (int i = 0; i < 8; i++) {
                    float av = (&a[i].x)[kq];
                    acc[i][0] += av * b4.x;  acc[i][1] += av * b4.y;
                    acc[i][2] += av * b4.z;  acc[i][3] += av * b4.w;
                }
            }
        }
        __syncthreads();
    }

#pragma unroll
    for (int i = 0; i < 8; i++) {
        int rr = m0 + ty * 8 + i;
        if (rr >= cnt) continue;
        int prr = g_rows[e * TT + rr];
        int tok = prr >> 1;
        float w = g_wpair[prr];
        float* orow = out + (size_t)tok * HH + n0 + tx * 4;
#pragma unroll
        for (int j = 0; j < 4; j++) atomicAdd(&orow[j], w * acc[i][j]);
    }
}

// ---------------------------------------------------------------------------
extern "C" void kernel_launch(void* const* d_in, const int* in_sizes, int n_in,
                              void* d_out, int out_size) {
    const float* x  = (const float*)d_in[0];   // hidden_states [B,S,H]
    const float* gw = (const float*)d_in[1];   // gate_w [E,H]
    const float* Wg = (const float*)d_in[2];   // [E,H,F]
    const float* Wu = (const float*)d_in[3];   // [E,H,F]
    const float* Wd = (const float*)d_in[4];   // [E,F,H]

    float* out    = (float*)d_out;                    // [T,H]
    float* logits = out + (size_t)TT * HH;            // [T,E]

    zero_kernel<<<(TT * HH + 255) / 256, 256>>>(out);
    router_kernel<<<TT / 8, 256>>>(x, gw, logits);
    gemm1_kernel<<<dim3(EE * MTILES, FF / BN), 256>>>(x, Wg, Wu);
    gemm2_kernel<<<dim3(EE * MTILES, HH / BN), 256>>>(Wd, out);
}

// round 14
// speedup vs baseline: 2.5833x; 2.5833x over previous
#include <cuda_runtime.h>
#include <math.h>
#include <stdint.h>

// Problem constants
#define TT 8192      // tokens = B*S
#define HH 1024      // hidden
#define FF 2048      // intermediate
#define EE 8         // experts

#define BM 128
#define BN 128
#define KC 32        // k-chunk (floats)
#define KCP 36       // padded smem k-stride (conflict-free fragment loads)

// Scratch (device globals — no allocation allowed). 256B-aligned: cp.async
// requires 16B-aligned gmem addresses and natural alignment is only 4B.
__device__ int   g_counts[EE];
__device__ int   g_rows[EE * TT];            // pair_row (=2*token+k) list per expert
__device__ float g_wpair[2 * TT];            // combine weight per pair
__device__ __align__(256) float g_xr[(size_t)TT * HH];      // x rounded to tf32 (rna)
__device__ __align__(256) float g_G[(size_t)2 * TT * FF];   // intermediate, tf32-rounded
__device__ __align__(256) float g_WgT[(size_t)EE * FF * HH];// Wg^T [E][F][H] (K-major)
__device__ __align__(256) float g_WuT[(size_t)EE * FF * HH];// Wu^T [E][F][H]
__device__ __align__(256) float g_WdT[(size_t)EE * HH * FF];// Wd^T [E][H][F]

// ---------------------------------------------------------------------------
__device__ __forceinline__ float rna_tf32(float f) {
    uint32_t r;
    asm("cvt.rna.tf32.f32 %0, %1;" : "=r"(r) : "f"(f));
    return __uint_as_float(r);
}

__device__ __forceinline__ void cp16(uint32_t s, const void* g) {
    asm volatile("cp.async.cg.shared.global [%0], [%1], 16;" :: "r"(s), "l"(g));
}
#define CP_COMMIT() asm volatile("cp.async.commit_group;")

__device__ __forceinline__ void mma8(float* c, const uint32_t* a, const uint32_t* b) {
    asm volatile(
        "mma.sync.aligned.m16n8k8.row.col.f32.tf32.tf32.f32 "
        "{%0,%1,%2,%3}, {%4,%5,%6,%7}, {%8,%9}, {%0,%1,%2,%3};"
        : "+f"(c[0]), "+f"(c[1]), "+f"(c[2]), "+f"(c[3])
        : "r"(a[0]), "r"(a[1]), "r"(a[2]), "r"(a[3]), "r"(b[0]), "r"(b[1]));
}

// ---------------------------------------------------------------------------
__global__ void zero_kernel(float* __restrict__ out) {
    int i = blockIdx.x * blockDim.x + threadIdx.x;
    if (i < TT * HH) out[i] = 0.0f;
    if (i < EE) g_counts[i] = 0;
}

// ---------------------------------------------------------------------------
// Weight transposes (+ tf32 rna rounding): 0 Wg->WgT, 1 Wu->WuT, 2 Wd->WdT
// src [E][R][C] -> dst [E][C][R]
// ---------------------------------------------------------------------------
__global__ void transpose_kernel(const float* __restrict__ src, int which, int R, int C) {
    __shared__ float t[32][33];
    float* dstb = (which == 0) ? g_WgT : (which == 1) ? g_WuT : g_WdT;
    int e = blockIdx.z;
    const float* S = src + (size_t)e * R * C;
    float* D = dstb + (size_t)e * R * C;
    int c0 = blockIdx.x * 32, r0 = blockIdx.y * 32;
    int tx = threadIdx.x & 31, ty = threadIdx.x >> 5;  // 32 x 8
#pragma unroll
    for (int i = 0; i < 32; i += 8)
        t[ty + i][tx] = S[(size_t)(r0 + ty + i) * C + c0 + tx];
    __syncthreads();
#pragma unroll
    for (int i = 0; i < 32; i += 8)
        D[(size_t)(c0 + ty + i) * R + r0 + tx] = rna_tf32(t[tx][ty + i]);
}

// ---------------------------------------------------------------------------
// Router: one warp per token; also writes tf32-rounded x copy.
// ---------------------------------------------------------------------------
__global__ void router_kernel(const float* __restrict__ x,
                              const float* __restrict__ gw,
                              float* __restrict__ logits_out) {
    int warp = (blockIdx.x * blockDim.x + threadIdx.x) >> 5;
    int lane = threadIdx.x & 31;
    if (warp >= TT) return;
    const float* xr = x + (size_t)warp * HH;
    float* xro = g_xr + (size_t)warp * HH;

    float acc[EE];
#pragma unroll
    for (int e = 0; e < EE; e++) acc[e] = 0.0f;

    for (int i = lane; i < HH; i += 32) {
        float xv = xr[i];
        xro[i] = rna_tf32(xv);
#pragma unroll
        for (int e = 0; e < EE; e++) acc[e] += xv * gw[e * HH + i];
    }
#pragma unroll
    for (int e = 0; e < EE; e++) {
#pragma unroll
        for (int off = 16; off; off >>= 1)
            acc[e] += __shfl_xor_sync(0xffffffffu, acc[e], off);
    }

    if (lane == 0) {
#pragma unroll
        for (int e = 0; e < EE; e++) logits_out[(size_t)warp * EE + e] = acc[e];

        float m = acc[0];
#pragma unroll
        for (int e = 1; e < EE; e++) m = fmaxf(m, acc[e]);
        float p[EE];
#pragma unroll
        for (int e = 0; e < EE; e++) p[e] = __expf(acc[e] - m);

        // top-2, lowest-index-first on ties (matches lax.top_k)
        int i1 = 0;
#pragma unroll
        for (int e = 1; e < EE; e++) if (p[e] > p[i1]) i1 = e;
        int i2 = (i1 == 0) ? 1 : 0;
#pragma unroll
        for (int e = 0; e < EE; e++) if (e != i1 && p[e] > p[i2]) i2 = e;

        float ws = p[i1] + p[i2];
        float w1 = p[i1] / ws;
        float w2 = p[i2] / ws;

        int r1 = atomicAdd(&g_counts[i1], 1);
        g_rows[i1 * TT + r1] = 2 * warp + 0;
        g_wpair[2 * warp + 0] = w1;
        int r2 = atomicAdd(&g_counts[i2], 1);
        g_rows[i2 * TT + r2] = 2 * warp + 1;
        g_wpair[2 * warp + 1] = w2;
    }
}

// ---------------------------------------------------------------------------
// GEMM1 (mma.sync tf32): gathered Xr [cnt,H] x WgT/WuT -> g_G = silu(g)*u
// 128x128 tile, 8 warps (2m x 4n), warp tile 64x32, dual accumulators.
// ---------------------------------------------------------------------------
#define TILEF (128 * KCP)            // floats per smem tile
#define G1_SMEM (6 * TILEF * 4)      // 110592 B
#define G2_SMEM (4 * TILEF * 4)      // 73728 B

__global__ __launch_bounds__(256, 1)
void gemm1_kernel() {
    extern __shared__ float sm[];
    float* As = sm;                  // [2][TILEF]
    float* Bg = sm + 2 * TILEF;
    float* Bu = sm + 4 * TILEF;

    const int e  = blockIdx.x >> 6;
    const int mt = blockIdx.x & 63;
    const int cnt = g_counts[e];
    const int m0 = mt * BM;
    if (m0 >= cnt) return;
    const int n0 = blockIdx.y * BN;

    uint32_t sbase;
    asm("{ .reg .u64 t; cvta.to.shared.u64 t, %1; cvt.u32.u64 %0, t; }"
        : "=r"(sbase) : "l"(sm));
    const int tid  = threadIdx.x;
    const int wid  = tid >> 5;
    const int lane = tid & 31;
    const int gid  = lane >> 2;      // fragment group row 0..7
    const int tig  = lane & 3;       // thread-in-group 0..3
    const int wm   = wid >> 2;       // 0..1
    const int wn   = wid & 3;        // 0..3

    // loader mapping: thread t -> row t>>1, 16-float half (t&1)
    const int lrow = tid >> 1;
    const int lc0  = (tid & 1) * 16;
    int ar = m0 + lrow; if (ar >= cnt) ar = cnt - 1;
    const int apr = g_rows[e * TT + ar];
    const float* axp = g_xr + (size_t)(apr >> 1) * HH + lc0;
    const float* bgp = g_WgT + ((size_t)e * FF + n0 + lrow) * HH + lc0;
    const float* bup = g_WuT + ((size_t)e * FF + n0 + lrow) * HH + lc0;
    const uint32_t soff = (uint32_t)(lrow * KCP + lc0) * 4;
    const uint32_t aS = sbase + soff;
    const uint32_t gS = sbase + 2 * TILEF * 4 + soff;
    const uint32_t uS = sbase + 4 * TILEF * 4 + soff;

    float accg[4][4][4], accu[4][4][4];
#pragma unroll
    for (int i = 0; i < 4; i++)
#pragma unroll
        for (int j = 0; j < 4; j++)
#pragma unroll
            for (int k = 0; k < 4; k++) { accg[i][j][k] = 0.f; accu[i][j][k] = 0.f; }

    // prologue: stage 0
#pragma unroll
    for (int i = 0; i < 4; i++) {
        cp16(aS + i * 16, axp + i * 4);
        cp16(gS + i * 16, bgp + i * 4);
        cp16(uS + i * 16, bup + i * 4);
    }
    CP_COMMIT();

    const int NS = HH / KC;   // 32
    for (int s = 0; s < NS; s++) {
        const int buf = s & 1;
        if (s + 1 < NS) {
            const int k1 = (s + 1) * KC;
            const uint32_t nb = (uint32_t)((buf ^ 1) * TILEF) * 4;
#pragma unroll
            for (int i = 0; i < 4; i++) {
                cp16(aS + nb + i * 16, axp + k1 + i * 4);
                cp16(gS + nb + i * 16, bgp + k1 + i * 4);
                cp16(uS + nb + i * 16, bup + k1 + i * 4);
            }
            CP_COMMIT();
            asm volatile("cp.async.wait_group 1;");
        } else {
            asm volatile("cp.async.wait_group 0;");
        }
        __syncthreads();

        const float* A  = As + buf * TILEF;
        const float* BG = Bg + buf * TILEF;
        const float* BU = Bu + buf * TILEF;
#pragma unroll
        for (int kk = 0; kk < KC; kk += 8) {
            uint32_t af[4][4];
#pragma unroll
            for (int mf = 0; mf < 4; mf++) {
                int r = wm * 64 + mf * 16 + gid;
                af[mf][0] = __float_as_uint(A[r * KCP + kk + tig]);
                af[mf][1] = __float_as_uint(A[(r + 8) * KCP + kk + tig]);
                af[mf][2] = __float_as_uint(A[r * KCP + kk + tig + 4]);
                af[mf][3] = __float_as_uint(A[(r + 8) * KCP + kk + tig + 4]);
            }
            uint32_t bgf[4][2], buf_[4][2];
#pragma unroll
            for (int nf = 0; nf < 4; nf++) {
                int n = wn * 32 + nf * 8 + gid;
                bgf[nf][0] = __float_as_uint(BG[n * KCP + kk + tig]);
                bgf[nf][1] = __float_as_uint(BG[n * KCP + kk + tig + 4]);
                buf_[nf][0] = __float_as_uint(BU[n * KCP + kk + tig]);
                buf_[nf][1] = __float_as_uint(BU[n * KCP + kk + tig + 4]);
            }
#pragma unroll
            for (int mf = 0; mf < 4; mf++)
#pragma unroll
                for (int nf = 0; nf < 4; nf++) {
                    mma8(accg[mf][nf], af[mf], bgf[nf]);
                    mma8(accu[mf][nf], af[mf], buf_[nf]);
                }
        }
        __syncthreads();
    }

    // epilogue: silu(g)*u, rna-round, scatter to g_G
#pragma unroll
    for (int mf = 0; mf < 4; mf++) {
#pragma unroll
        for (int rs = 0; rs < 2; rs++) {
            int rr = m0 + wm * 64 + mf * 16 + rs * 8 + gid;
            if (rr >= cnt) continue;
            int prr = g_rows[e * TT + rr];
            float* dst = g_G + (size_t)prr * FF + n0 + wn * 32;
#pragma unroll
            for (int nf = 0; nf < 4; nf++) {
                float gv0 = accg[mf][nf][rs * 2 + 0];
                float gv1 = accg[mf][nf][rs * 2 + 1];
                float uv0 = accu[mf][nf][rs * 2 + 0];
                float uv1 = accu[mf][nf][rs * 2 + 1];
                float2 o;
                o.x = rna_tf32(gv0 / (1.0f + __expf(-gv0)) * uv0);
                o.y = rna_tf32(gv1 / (1.0f + __expf(-gv1)) * uv1);
                *(float2*)(dst + nf * 8 + tig * 2) = o;
            }
        }
    }
}

// ---------------------------------------------------------------------------
// GEMM2 (mma.sync tf32): G rows [cnt,F] x WdT -> weighted atomicAdd into out
// ---------------------------------------------------------------------------
__global__ __launch_bounds__(256, 2)
void gemm2_kernel(float* __restrict__ out) {
    extern __shared__ float sm[];
    float* As = sm;                  // [2][TILEF]
    float* Bs = sm + 2 * TILEF;

    const int e  = blockIdx.x >> 6;
    const int mt = blockIdx.x & 63;
    const int cnt = g_counts[e];
    const int m0 = mt * BM;
    if (m0 >= cnt) return;
    const int n0 = blockIdx.y * BN;

    uint32_t sbase;
    asm("{ .reg .u64 t; cvta.to.shared.u64 t, %1; cvt.u32.u64 %0, t; }"
        : "=r"(sbase) : "l"(sm));
    const int tid  = threadIdx.x;
    const int wid  = tid >> 5;
    const int lane = tid & 31;
    const int gid  = lane >> 2;
    const int tig  = lane & 3;
    const int wm   = wid >> 2;
    const int wn   = wid & 3;

    const int lrow = tid >> 1;
    const int lc0  = (tid & 1) * 16;
    int ar = m0 + lrow; if (ar >= cnt) ar = cnt - 1;
    const int apr = g_rows[e * TT + ar];
    const float* axp = g_G + (size_t)apr * FF + lc0;
    const float* bdp = g_WdT + ((size_t)e * HH + n0 + lrow) * FF + lc0;
    const uint32_t soff = (uint32_t)(lrow * KCP + lc0) * 4;
    const uint32_t aS = sbase + soff;
    const uint32_t bS = sbase + 2 * TILEF * 4 + soff;

    float acc[4][4][4];
#pragma unroll
    for (int i = 0; i < 4; i++)
#pragma unroll
        for (int j = 0; j < 4; j++)
#pragma unroll
            for (int k = 0; k < 4; k++) acc[i][j][k] = 0.f;

#pragma unroll
    for (int i = 0; i < 4; i++) {
        cp16(aS + i * 16, axp + i * 4);
        cp16(bS + i * 16, bdp + i * 4);
    }
    CP_COMMIT();

    const int NS = FF / KC;  // 64
    for (int s = 0; s < NS; s++) {
        const int buf = s & 1;
        if (s + 1 < NS) {
            const int k1 = (s + 1) * KC;
            const uint32_t nb = (uint32_t)((buf ^ 1) * TILEF) * 4;
#pragma unroll
            for (int i = 0; i < 4; i++) {
                cp16(aS + nb + i * 16, axp + k1 + i * 4);
                cp16(bS + nb + i * 16, bdp + k1 + i * 4);
            }
            CP_COMMIT();
            asm volatile("cp.async.wait_group 1;");
        } else {
            asm volatile("cp.async.wait_group 0;");
        }
        __syncthreads();

        const float* A = As + buf * TILEF;
        const float* B = Bs + buf * TILEF;
#pragma unroll
        for (int kk = 0; kk < KC; kk += 8) {
            uint32_t af[4][4];
#pragma unroll
            for (int mf = 0; mf < 4; mf++) {
                int r = wm * 64 + mf * 16 + gid;
                af[mf][0] = __float_as_uint(A[r * KCP + kk + tig]);
                af[mf][1] = __float_as_uint(A[(r + 8) * KCP + kk + tig]);
                af[mf][2] = __float_as_uint(A[r * KCP + kk + tig + 4]);
                af[mf][3] = __float_as_uint(A[(r + 8) * KCP + kk + tig + 4]);
            }
            uint32_t bf[4][2];
#pragma unroll
            for (int nf = 0; nf < 4; nf++) {
                int n = wn * 32 + nf * 8 + gid;
                bf[nf][0] = __float_as_uint(B[n * KCP + kk + tig]);
                bf[nf][1] = __float_as_uint(B[n * KCP + kk + tig + 4]);
            }
#pragma unroll
            for (int mf = 0; mf < 4; mf++)
#pragma unroll
                for (int nf = 0; nf < 4; nf++)
                    mma8(acc[mf][nf], af[mf], bf[nf]);
        }
        __syncthreads();
    }

#pragma unroll
    for (int mf = 0; mf < 4; mf++) {
#pragma unroll
        for (int rs = 0; rs < 2; rs++) {
            int rr = m0 + wm * 64 + mf * 16 + rs * 8 + gid;
            if (rr >= cnt) continue;
            int prr = g_rows[e * TT + rr];
            int tok = prr >> 1;
            float w = g_wpair[prr];
            float* orow = out + (size_t)tok * HH + n0 + wn * 32;
#pragma unroll
            for (int nf = 0; nf < 4; nf++) {
                atomicAdd(&orow[nf * 8 + tig * 2 + 0], w * acc[mf][nf][rs * 2 + 0]);
                atomicAdd(&orow[nf * 8 + tig * 2 + 1], w * acc[mf][nf][rs * 2 + 1]);
            }
        }
    }
}

// ---------------------------------------------------------------------------
extern "C" void kernel_launch(void* const* d_in, const int* in_sizes, int n_in,
                              void* d_out, int out_size) {
    const float* x  = (const float*)d_in[0];   // hidden_states [B,S,H]
    const float* gw = (const float*)d_in[1];   // gate_w [E,H]
    const float* Wg = (const float*)d_in[2];   // [E,H,F]
    const float* Wu = (const float*)d_in[3];   // [E,H,F]
    const float* Wd = (const float*)d_in[4];   // [E,F,H]

    float* out    = (float*)d_out;             // [T,H]
    float* logits = out + (size_t)TT * HH;     // [T,E]

    cudaFuncSetAttribute(gemm1_kernel, cudaFuncAttributeMaxDynamicSharedMemorySize, G1_SMEM);
    cudaFuncSetAttribute(gemm2_kernel, cudaFuncAttributeMaxDynamicSharedMemorySize, G2_SMEM);

    zero_kernel<<<(TT * HH + 255) / 256, 256>>>(out);
    transpose_kernel<<<dim3(FF / 32, HH / 32, EE), 256>>>(Wg, 0, HH, FF);
    transpose_kernel<<<dim3(FF / 32, HH / 32, EE), 256>>>(Wu, 1, HH, FF);
    transpose_kernel<<<dim3(HH / 32, FF / 32, EE), 256>>>(Wd, 2, FF, HH);
    router_kernel<<<TT / 8, 256>>>(x, gw, logits);
    gemm1_kernel<<<dim3(EE * 64, FF / BN), 256, G1_SMEM>>>();
    gemm2_kernel<<<dim3(EE * 64, HH / BN), 256, G2_SMEM>>>(out);
}